// round 14
// baseline (speedup 1.0000x reference)
#include <cuda_runtime.h>
#include <cuda.h>
#include <cstdint>
#include <cstddef>

#define E_EXP 16
#define T_TOK 512
#define H_DIM 1024
#define I_DIM 4096

// Does this device-compilation pass support tcgen05 (arch-specific sm_10xa)?
#if defined(__CUDA_ARCH__) && (defined(__CUDA_ARCH_FEAT_SM103_ALL) || defined(__CUDA_ARCH_FEAT_SM100_ALL) || defined(__CUDA_ARCH_FEAT_SM101_ALL) || defined(__CUDA_ARCH_SPECIFIC__))
#define TCGEN_OK 1
#else
#define TCGEN_OK 0
#endif

// Scratch (__device__ globals: allocation-free rule)
__device__ float g_Xr [(size_t)E_EXP * T_TOK * H_DIM];   // rounded X        [e][t][h]
__device__ float g_W1t[(size_t)E_EXP * I_DIM * H_DIM];   // rounded W1^T     [e][i][h]
__device__ float g_W2t[(size_t)E_EXP * H_DIM * I_DIM];   // rounded W2^T     [e][h][i]
__device__ float g_h  [(size_t)E_EXP * T_TOK * I_DIM];   // intermediate (tf32-rounded)

// ---------------- common helpers ----------------
__device__ __forceinline__ uint32_t smem_to_u32(const void* p) {
    uint32_t a;
    asm("{ .reg .u64 t; cvta.to.shared.u64 t, %1; cvt.u32.u64 %0, t; }" : "=r"(a) : "l"(p));
    return a;
}
// RN-round fp32 -> tf32 bit pattern (low 13 bits zero); exact no-op for HW cvt
__device__ __forceinline__ float rn_tf32(float x) {
    uint32_t b = __float_as_uint(x);
    b = (b + 0xFFFu + ((b >> 13) & 1u)) & 0xFFFFE000u;
    return __uint_as_float(b);
}

#define CLUSTER_SYNC() do { \
    asm volatile("barrier.cluster.arrive.aligned;" ::: "memory"); \
    asm volatile("barrier.cluster.wait.aligned;" ::: "memory"); \
} while (0)

#if TCGEN_OK
// ---------------- tcgen05/TMA helpers (sm_103a pass only) ----------------
__device__ __forceinline__ uint32_t elect_one_pred() {
    uint32_t pred;
    asm volatile("{\n\t.reg .pred p;\n\telect.sync _|p, 0xFFFFFFFF;\n\tselp.b32 %0, 1, 0, p;\n\t}" : "=r"(pred));
    return pred;
}
#define MBARRIER_INIT(addr, count) \
    asm volatile("mbarrier.init.shared.b64 [%0], %1;" :: "r"((uint32_t)(addr)), "r"((uint32_t)(count)) : "memory")
#define MBARRIER_EXPECT_TX(addr, bytes) \
    asm volatile("mbarrier.arrive.expect_tx.shared.b64 _, [%0], %1;" :: "r"((uint32_t)(addr)), "r"((uint32_t)(bytes)) : "memory")
#define MBARRIER_WAIT_PARITY(a, pp) do { \
    uint32_t _m = (uint32_t)(a); uint32_t _p = (uint32_t)(pp); uint32_t _d; \
    asm volatile("{\n\t.reg .pred p;\n\tmbarrier.try_wait.parity.acquire.cta.shared::cta.b64 p, [%1], %2;\n\tselp.b32 %0, 1, 0, p;\n\t}" \
        : "=r"(_d) : "r"(_m), "r"(_p) : "memory"); \
    if (!_d) { \
        asm volatile("{\n\t.reg .pred P1;\n\tWL_%=:\n\tmbarrier.try_wait.parity.acquire.cta.shared::cta.b64 P1, [%0], %1, 0x989680;\n\t@P1 bra.uni WD_%=;\n\tbra.uni WL_%=;\n\tWD_%=:\n\t}" \
            :: "r"(_m), "r"(_p) : "memory"); \
    } \
} while (0)
#define TCGEN05_ALLOC(sa, n) \
    asm volatile("tcgen05.alloc.cta_group::1.sync.aligned.shared::cta.b32 [%0], %1;" :: "r"((uint32_t)(sa)), "r"((uint32_t)(n)) : "memory")
#define TCGEN05_DEALLOC(t, n) \
    asm volatile("tcgen05.dealloc.cta_group::1.sync.aligned.b32 %0, %1;" :: "r"(t), "r"((uint32_t)(n)))
#define TCGEN05_RELINQ() asm volatile("tcgen05.relinquish_alloc_permit.cta_group::1.sync.aligned;")
#define TCGEN05_COMMIT(m) \
    asm volatile("tcgen05.commit.cta_group::1.mbarrier::arrive::one.shared::cluster.b64 [%0];" :: "r"((uint32_t)(m)) : "memory")
#define TCGEN05_COMMIT_MULTICAST(m, mask) \
    asm volatile("tcgen05.commit.cta_group::1.mbarrier::arrive::one.shared::cluster.multicast::cluster.b64 [%0], %1;" \
                 :: "r"((uint32_t)(m)), "h"((uint16_t)(mask)) : "memory")
#define TCGEN05_WAIT_LD()  asm volatile("tcgen05.wait::ld.sync.aligned;" ::: "memory")
#define TCGEN05_FENCE_BEFORE() asm volatile("tcgen05.fence::before_thread_sync;" ::: "memory")
#define TCGEN05_FENCE_AFTER()  asm volatile("tcgen05.fence::after_thread_sync;" ::: "memory")
#define FENCE_ASYNC() asm volatile("fence.proxy.async.shared::cta;" ::: "memory")

#define TMA_LOAD_3D(smem_addr, tensor_map, cx, cy, cz, mbar) \
    asm volatile("cp.async.bulk.tensor.3d.shared::cta.global.tile.mbarrier::complete_tx::bytes " \
                 "[%0], [%1, {%2, %3, %4}], [%5];" \
                 :: "r"((uint32_t)(smem_addr)), "l"(tensor_map), \
                    "r"((int32_t)(cx)), "r"((int32_t)(cy)), "r"((int32_t)(cz)), \
                    "r"((uint32_t)(mbar)) : "memory")

#define TMA_LOAD_3D_MULTICAST(smem_addr, tensor_map, cx, cy, cz, mbar, mask) \
    asm volatile("cp.async.bulk.tensor.3d.shared::cluster.global.tile.mbarrier::complete_tx::bytes.multicast::cluster " \
                 "[%0], [%1, {%2, %3, %4}], [%5], %6;" \
                 :: "r"((uint32_t)(smem_addr)), "l"(tensor_map), \
                    "r"((int32_t)(cx)), "r"((int32_t)(cy)), "r"((int32_t)(cz)), \
                    "r"((uint32_t)(mbar)), "h"((uint16_t)(mask)) : "memory")

#define TCGEN05_LD_32X32B_X32(r, ta) \
    asm volatile("tcgen05.ld.sync.aligned.32x32b.x32.b32 " \
        "{%0, %1, %2, %3, %4, %5, %6, %7, %8, %9, %10, %11, %12, %13, %14, %15, " \
        " %16, %17, %18, %19, %20, %21, %22, %23, %24, %25, %26, %27, %28, %29, %30, %31}, [%32];" \
        : "=r"((r)[0]),  "=r"((r)[1]),  "=r"((r)[2]),  "=r"((r)[3]), \
          "=r"((r)[4]),  "=r"((r)[5]),  "=r"((r)[6]),  "=r"((r)[7]), \
          "=r"((r)[8]),  "=r"((r)[9]),  "=r"((r)[10]), "=r"((r)[11]), \
          "=r"((r)[12]), "=r"((r)[13]), "=r"((r)[14]), "=r"((r)[15]), \
          "=r"((r)[16]), "=r"((r)[17]), "=r"((r)[18]), "=r"((r)[19]), \
          "=r"((r)[20]), "=r"((r)[21]), "=r"((r)[22]), "=r"((r)[23]), \
          "=r"((r)[24]), "=r"((r)[25]), "=r"((r)[26]), "=r"((r)[27]), \
          "=r"((r)[28]), "=r"((r)[29]), "=r"((r)[30]), "=r"((r)[31]) \
        : "r"(ta))

static constexpr uint64_t DESC_SW128 =
    (uint64_t(2) << 61) | (uint64_t(1) << 46) | (uint64_t(64) << 32) | (uint64_t(1) << 16);
#define MAKE_DESC(a) (DESC_SW128 | ((uint64_t)((a) >> 4) & 0x3FFF))

__device__ __forceinline__ void mma_tf32_ss(uint32_t d, uint64_t ad, uint64_t bd,
                                            uint32_t idesc, uint32_t en) {
    asm volatile("{\n\t.reg .pred p;\n\tsetp.ne.u32 p, %4, 0;\n\t"
        "tcgen05.mma.cta_group::1.kind::tf32 [%0], %1, %2, %3, {%5, %5, %5, %5}, p;\n\t}"
        :: "r"(d), "l"(ad), "l"(bd), "r"(idesc), "r"(en), "r"(0u) : "memory");
}
#endif // TCGEN_OK

// ---------------- Prep: round X ----------------
__global__ void round_x_kernel(const float4* __restrict__ in) {
    size_t i = (size_t)blockIdx.x * blockDim.x + threadIdx.x;
    float4 v = in[i];
    v.x = rn_tf32(v.x); v.y = rn_tf32(v.y); v.z = rn_tf32(v.z); v.w = rn_tf32(v.w);
    reinterpret_cast<float4*>(g_Xr)[i] = v;
}

// ---------------- Prep: round + transpose weights to [n][k] ----------------
template <int WHICH>
__global__ void transpose_round_kernel(const float* __restrict__ in) {
    constexpr int R = (WHICH == 0) ? H_DIM : I_DIM;  // input rows (k)
    constexpr int C = (WHICH == 0) ? I_DIM : H_DIM;  // input cols (n)
    float* out = (WHICH == 0) ? g_W1t : g_W2t;
    __shared__ float tile[32][33];
    int e = blockIdx.z;
    const float* pin = in + (size_t)e * R * C;
    float* pout = out + (size_t)e * R * C;
    int tx = threadIdx.x, ty = threadIdx.y;
    int c0 = blockIdx.x * 32, r0 = blockIdx.y * 32;
#pragma unroll
    for (int j = 0; j < 4; j++)
        tile[ty + j * 8][tx] = rn_tf32(pin[(size_t)(r0 + ty + j * 8) * C + c0 + tx]);
    __syncthreads();
#pragma unroll
    for (int j = 0; j < 4; j++)
        pout[(size_t)(c0 + ty + j * 8) * R + r0 + tx] = tile[tx][ty + j * 8];
}

// ============================================================================
// Grouped GEMM: C[e,m,n] = sum_k A[e,m,k]*B[e,n,k] + bias[e,n]
// CTA tile 128x256, KC=32, STAGES=2, 2 CTAs/SM, cluster (8,1,1) = 4mt x 2nt.
// 2-D cooperative TMA multicast:
//   A tile (per mt) shared by the 2 nt-CTAs: 2 slices of 64 rows, mask 0x11<<mt
//   B tile (per nt) shared by the 4 mt-CTAs: 4 slices of 64 rows, mask 0xF<<(4*ntLo)
// L2 traffic: GEMM1 768 MB -> 512 MB vs R13 (A was the dominant term).
// empty[s] cluster-wide (count=8, commit-multicast 0xFF): every producer
// multicasts into every peer's stage buffers, so all 8 must retire first.
// WHICH=0: A=g_Xr (K=H), B=g_W1t, N=I, C=g_h (rounded)
// WHICH=1: A=g_h  (K=I), B=g_W2t, N=H, C=out
// ============================================================================
template <int KT, int NTOT, int WHICH>
__global__ __launch_bounds__(256, 2) __cluster_dims__(8, 1, 1)
void gemm_tf32_kernel(const __grid_constant__ CUtensorMap tmA,
                      const __grid_constant__ CUtensorMap tmB,
                      const float* __restrict__ bias, float* __restrict__ outC) {
    constexpr int TM = 128, TN = 256, KC = 32, STAGES = 2;
    constexpr int ABYTES = TM * KC * 4;   // 16 KB
    constexpr int BBYTES = TN * KC * 4;   // 32 KB
    constexpr int ASLICE = (TM / 2) * KC * 4;  // 8 KB (1024B-atom aligned)
    constexpr int BSLICE = (TN / 4) * KC * 4;  // 8 KB
    constexpr int KITERS = KT / KC;

    float* Cb = (WHICH == 0) ? g_h : outC;

    extern __shared__ char smem[];
    uint32_t sbase = smem_to_u32(smem);
    float* bias_s = (float*)(smem + 2048);              // 256 floats
    uint32_t tiles = (sbase + 3072 + 1023) & ~1023u;    // 1024-aligned

    int tid = threadIdx.x, wid = tid >> 5, lane = tid & 31;
    // cluster-of-8 decomposition: blockIdx.x = ntLo*4 + mt
    int mt   = blockIdx.x & 3;
    int ntLo = (blockIdx.x >> 2) & 1;
    int nt   = blockIdx.y * 2 + ntLo;
    int e    = blockIdx.z;

    if (tid < TN) bias_s[tid] = bias[(size_t)e * NTOT + (size_t)nt * TN + tid];

#if TCGEN_OK
    constexpr uint32_t IDESC =
        (1u << 4) | (2u << 7) | (2u << 10) | ((TN / 8) << 17) | ((TM / 16) << 24);
    uint32_t full0  = sbase;          // STAGES x 8B
    uint32_t empty0 = sbase + 64;     // STAGES x 8B
    uint32_t doneb  = sbase + 128;
    uint32_t tslot  = sbase + 136;

    const uint16_t maskA = (uint16_t)(0x11u << mt);        // {mt, mt+4}
    const uint16_t maskB = (uint16_t)(0xFu << (ntLo * 4)); // {4*ntLo .. 4*ntLo+3}

    if (tid == 0) {
#pragma unroll
        for (int s = 0; s < STAGES; s++) {
            MBARRIER_INIT(full0 + 8 * s, 1);    // flips via expect_tx(48KB) + slices
            MBARRIER_INIT(empty0 + 8 * s, 8);   // 8 cluster commit-multicast arrivals
        }
        MBARRIER_INIT(doneb, 1);
        FENCE_ASYNC();
    }
    if (wid == 7) {
        TCGEN05_ALLOC(tslot, 256);   // 2 CTAs x 256 = 512 cols/SM
        TCGEN05_RELINQ();            // release permit so co-resident CTA can alloc
    }
    __syncthreads();
    // all cluster CTAs' mbarriers must exist before any multicast targets them
    CLUSTER_SYNC();

    uint32_t tmem;
    asm volatile("ld.shared.b32 %0, [%1];" : "=r"(tmem) : "r"(tslot));

    if (wid == 6 && elect_one_pred()) {
        // ---- producer: A slice (64 rows) -> 2 nt-peers; B slice (64 rows) -> 4 mt-peers
#pragma unroll 1
        for (int it = 0; it < KITERS; ++it) {
            int s = it & (STAGES - 1);
            // cluster-wide empty: all 8 CTAs retired stage s
            MBARRIER_WAIT_PARITY(empty0 + 8 * s, 1 ^ ((it / STAGES) & 1));
            uint32_t fb = full0 + 8 * s;
            MBARRIER_EXPECT_TX(fb, ABYTES + BBYTES);   // 2 A-slices + 4 B-slices inbound
            TMA_LOAD_3D_MULTICAST(tiles + s * ABYTES + ntLo * ASLICE,
                                  &tmA, it * KC, mt * TM + ntLo * (TM / 2), e, fb, maskA);
            TMA_LOAD_3D_MULTICAST(tiles + STAGES * ABYTES + s * BBYTES + mt * BSLICE,
                                  &tmB, it * KC, nt * TN + mt * (TN / 4), e, fb, maskB);
        }
    }
    if (wid == 7 && elect_one_pred()) {
        // -------- MMA issuer --------
#pragma unroll 1
        for (int it = 0; it < KITERS; ++it) {
            int s = it & (STAGES - 1);
            MBARRIER_WAIT_PARITY(full0 + 8 * s, (it / STAGES) & 1);
            uint64_t ad = MAKE_DESC(tiles + s * ABYTES);
            uint64_t bd = MAKE_DESC(tiles + STAGES * ABYTES + s * BBYTES);
#pragma unroll
            for (int k = 0; k < 4; k++)   // 4 x K=8 tf32 dispatches, +32B each
                mma_tf32_ss(tmem, ad + 2 * k, bd + 2 * k, IDESC,
                            (it > 0 || k > 0) ? 1u : 0u);
            // stage s free -> tell all 8 cluster CTAs (their producers multicast into us)
            TCGEN05_COMMIT_MULTICAST(empty0 + 8 * s, 0xFF);
        }
        TCGEN05_COMMIT(doneb);
    }

    // epilogue: warps 0-3 read TMEM rows, add bias, store
    if (wid < 4) {
        MBARRIER_WAIT_PARITY(doneb, 0);
        TCGEN05_FENCE_AFTER();
        float* Crow = Cb + ((size_t)(e * T_TOK + mt * TM + wid * 32 + lane)) * NTOT
                         + (size_t)nt * TN;
#pragma unroll 1
        for (int c0 = 0; c0 < TN / 32; c0++) {
            uint32_t regs[32];
            TCGEN05_LD_32X32B_X32(regs, tmem + c0 * 32);
            TCGEN05_WAIT_LD();
            float4 v[8];
#pragma unroll
            for (int j = 0; j < 32; j++) {
                float x = __uint_as_float(regs[j]) + bias_s[c0 * 32 + j];
                if (WHICH == 0) x = rn_tf32(x);
                ((float*)v)[j] = x;
            }
#pragma unroll
            for (int q = 0; q < 8; q++)
                reinterpret_cast<float4*>(Crow + c0 * 32)[q] = v[q];
        }
        TCGEN05_FENCE_BEFORE();
    }
    __syncthreads();
    // no CTA may exit while peers' multicast TMA / commit-multicast can still
    // target its SMEM. Each CTA's doneb-wait ordered all its commit arrivals.
    CLUSTER_SYNC();
    if (wid == 7) {
        TCGEN05_DEALLOC(tmem, 256);
    }
#else
    // Fallback (base sm_103 compile pass; never selected at runtime on GB300):
    // correct but slow scalar GEMM so the fat binary stays semantically valid.
    const float* A = (WHICH == 0) ? g_Xr : g_h;
    const float* B = (WHICH == 0) ? g_W1t : g_W2t;
    const float* Ab = A + ((size_t)e * T_TOK + (size_t)mt * TM) * KT;
    const float* Bb = B + ((size_t)e * NTOT + (size_t)nt * TN) * KT;
    __syncthreads();
    for (int idx = tid; idx < TM * TN; idx += 256) {
        int m = idx / TN, n = idx % TN;
        float s = bias_s[n];
        const float* a = Ab + (size_t)m * KT;
        const float* b = Bb + (size_t)n * KT;
        for (int k = 0; k < KT; k++) s += a[k] * b[k];
        if (WHICH == 0) s = rn_tf32(s);
        Cb[((size_t)(e * T_TOK + mt * TM + m)) * NTOT + (size_t)nt * TN + n] = s;
    }
#endif
}

// ---------------- host: tensormap building ----------------
typedef CUresult (*PFN_tmEncode)(CUtensorMap*, CUtensorMapDataType, cuuint32_t, void*,
                                 const cuuint64_t*, const cuuint64_t*, const cuuint32_t*,
                                 const cuuint32_t*, CUtensorMapInterleave, CUtensorMapSwizzle,
                                 CUtensorMapL2promotion, CUtensorMapFloatOOBfill);

static void make_map_f32(PFN_tmEncode enc, CUtensorMap* m, void* base,
                         uint64_t d0, uint64_t d1, uint64_t d2,
                         uint32_t b0, uint32_t b1) {
    cuuint64_t dims[3]    = {d0, d1, d2};
    cuuint64_t strides[2] = {d0 * 4, d0 * d1 * 4};
    cuuint32_t box[3]     = {b0, b1, 1};
    cuuint32_t es[3]      = {1, 1, 1};
    enc(m, CU_TENSOR_MAP_DATA_TYPE_FLOAT32, 3, base, dims, strides, box, es,
        CU_TENSOR_MAP_INTERLEAVE_NONE, CU_TENSOR_MAP_SWIZZLE_128B,
        CU_TENSOR_MAP_L2_PROMOTION_L2_128B, CU_TENSOR_MAP_FLOAT_OOB_FILL_NONE);
}

// ---------------- launch ----------------
extern "C" void kernel_launch(void* const* d_in, const int* in_sizes, int n_in,
                              void* d_out, int out_size) {
    const float* X  = (const float*)d_in[0];
    const float* W1 = (const float*)d_in[1];
    const float* b1 = (const float*)d_in[2];
    const float* W2 = (const float*)d_in[3];
    const float* b2 = (const float*)d_in[4];
    float* out = (float*)d_out;

    // One-time resources (created on the eager correctness call, reused in capture)
    static PFN_tmEncode enc = nullptr;
    static CUtensorMap tmA1, tmB1, tmA2, tmB2;
    constexpr int SMEM = 4096 + 2 * (128 * 32 * 4 + 256 * 32 * 4);  // 102400
    if (!enc) {
        void* fn = nullptr;
        cudaDriverEntryPointQueryResult qres;
        cudaGetDriverEntryPoint("cuTensorMapEncodeTiled", &fn, cudaEnableDefault, &qres);
        enc = (PFN_tmEncode)fn;

        void *pXr = nullptr, *pW1t = nullptr, *pW2t = nullptr, *pH = nullptr;
        cudaGetSymbolAddress(&pXr, g_Xr);
        cudaGetSymbolAddress(&pW1t, g_W1t);
        cudaGetSymbolAddress(&pW2t, g_W2t);
        cudaGetSymbolAddress(&pH, g_h);
        // boxes are cooperative multicast slices: A (32 k-floats, 64 m-rows),
        // B (32 k-floats, 64 n-rows)
        make_map_f32(enc, &tmA1, pXr,  H_DIM, T_TOK, E_EXP, 32, 64);  // X   [e][t][h]
        make_map_f32(enc, &tmB1, pW1t, H_DIM, I_DIM, E_EXP, 32, 64);  // W1t [e][i][h]
        make_map_f32(enc, &tmA2, pH,   I_DIM, T_TOK, E_EXP, 32, 64);  // h   [e][t][i]
        make_map_f32(enc, &tmB2, pW2t, I_DIM, H_DIM, E_EXP, 32, 64);  // W2t [e][h][i]

        cudaFuncSetAttribute(gemm_tf32_kernel<H_DIM, I_DIM, 0>,
                             cudaFuncAttributeMaxDynamicSharedMemorySize, SMEM);
        cudaFuncSetAttribute(gemm_tf32_kernel<I_DIM, H_DIM, 1>,
                             cudaFuncAttributeMaxDynamicSharedMemorySize, SMEM);
    }

    // prep (serial, single stream)
    round_x_kernel<<<(E_EXP * T_TOK * H_DIM) / (4 * 256), 256>>>((const float4*)X);
    transpose_round_kernel<0><<<dim3(I_DIM / 32, H_DIM / 32, E_EXP), dim3(32, 8)>>>(W1);
    transpose_round_kernel<1><<<dim3(H_DIM / 32, I_DIM / 32, E_EXP), dim3(32, 8)>>>(W2);

    // GEMM1: h = X @ W1 + b1   (grid 8 x 8 x 16; clusters of 8 = 4mt x 2nt)
    gemm_tf32_kernel<H_DIM, I_DIM, 0>
        <<<dim3(8, I_DIM / 256 / 2, E_EXP), 256, SMEM>>>(tmA1, tmB1, b1, nullptr);
    // GEMM2: y = h @ W2 + b2   (grid 8 x 2 x 16)
    gemm_tf32_kernel<I_DIM, H_DIM, 1>
        <<<dim3(8, H_DIM / 256 / 2, E_EXP), 256, SMEM>>>(tmA2, tmB2, b2, out);
}

// round 16
// speedup vs baseline: 1.0384x; 1.0384x over previous
#include <cuda_runtime.h>
#include <cuda.h>
#include <cstdint>
#include <cstddef>

#define E_EXP 16
#define T_TOK 512
#define H_DIM 1024
#define I_DIM 4096

#if defined(__CUDA_ARCH__) && (defined(__CUDA_ARCH_FEAT_SM103_ALL) || defined(__CUDA_ARCH_FEAT_SM100_ALL) || defined(__CUDA_ARCH_FEAT_SM101_ALL) || defined(__CUDA_ARCH_SPECIFIC__))
#define TCGEN_OK 1
#else
#define TCGEN_OK 0
#endif

// Scratch (__device__ globals: allocation-free rule)
__device__ float g_Xr [(size_t)E_EXP * T_TOK * H_DIM];   // rounded X        [e][t][h]
__device__ float g_W1t[(size_t)E_EXP * I_DIM * H_DIM];   // rounded W1^T     [e][i][h]
__device__ float g_W2t[(size_t)E_EXP * H_DIM * I_DIM];   // rounded W2^T     [e][h][i]
__device__ float g_h  [(size_t)E_EXP * T_TOK * I_DIM];   // intermediate (tf32-rounded)

// ---------------- common helpers ----------------
__device__ __forceinline__ uint32_t smem_to_u32(const void* p) {
    uint32_t a;
    asm("{ .reg .u64 t; cvta.to.shared.u64 t, %1; cvt.u32.u64 %0, t; }" : "=r"(a) : "l"(p));
    return a;
}
// RN-round fp32 -> tf32 bit pattern (low 13 bits zero); exact no-op for HW cvt
__device__ __forceinline__ float rn_tf32(float x) {
    uint32_t b = __float_as_uint(x);
    b = (b + 0xFFFu + ((b >> 13) & 1u)) & 0xFFFFE000u;
    return __uint_as_float(b);
}

#define CLUSTER_SYNC() do { \
    asm volatile("barrier.cluster.arrive.aligned;" ::: "memory"); \
    asm volatile("barrier.cluster.wait.aligned;" ::: "memory"); \
} while (0)

#if TCGEN_OK
// ---------------- tcgen05/TMA helpers (sm_103a pass only) ----------------
__device__ __forceinline__ uint32_t elect_one_pred() {
    uint32_t pred;
    asm volatile("{\n\t.reg .pred p;\n\telect.sync _|p, 0xFFFFFFFF;\n\tselp.b32 %0, 1, 0, p;\n\t}" : "=r"(pred));
    return pred;
}
#define MBARRIER_INIT(addr, count) \
    asm volatile("mbarrier.init.shared.b64 [%0], %1;" :: "r"((uint32_t)(addr)), "r"((uint32_t)(count)) : "memory")
#define MBARRIER_EXPECT_TX(addr, bytes) \
    asm volatile("mbarrier.arrive.expect_tx.shared.b64 _, [%0], %1;" :: "r"((uint32_t)(addr)), "r"((uint32_t)(bytes)) : "memory")
#define MBARRIER_WAIT_PARITY(a, pp) do { \
    uint32_t _m = (uint32_t)(a); uint32_t _p = (uint32_t)(pp); uint32_t _d; \
    asm volatile("{\n\t.reg .pred p;\n\tmbarrier.try_wait.parity.acquire.cta.shared::cta.b64 p, [%1], %2;\n\tselp.b32 %0, 1, 0, p;\n\t}" \
        : "=r"(_d) : "r"(_m), "r"(_p) : "memory"); \
    if (!_d) { \
        asm volatile("{\n\t.reg .pred P1;\n\tWL_%=:\n\tmbarrier.try_wait.parity.acquire.cta.shared::cta.b64 P1, [%0], %1, 0x989680;\n\t@P1 bra.uni WD_%=;\n\tbra.uni WL_%=;\n\tWD_%=:\n\t}" \
            :: "r"(_m), "r"(_p) : "memory"); \
    } \
} while (0)
// cta_group::2 TMEM management (collective across the pair)
#define TCGEN05_ALLOC_CG2(sa, n) \
    asm volatile("tcgen05.alloc.cta_group::2.sync.aligned.shared::cta.b32 [%0], %1;" :: "r"((uint32_t)(sa)), "r"((uint32_t)(n)) : "memory")
#define TCGEN05_DEALLOC_CG2(t, n) \
    asm volatile("tcgen05.dealloc.cta_group::2.sync.aligned.b32 %0, %1;" :: "r"(t), "r"((uint32_t)(n)))
#define TCGEN05_RELINQ_CG2() asm volatile("tcgen05.relinquish_alloc_permit.cta_group::2.sync.aligned;")
#define TCGEN05_COMMIT_MULTICAST_CG2(m, mask) \
    asm volatile("tcgen05.commit.cta_group::2.mbarrier::arrive::one.shared::cluster.multicast::cluster.b64 [%0], %1;" \
                 :: "r"((uint32_t)(m)), "h"((uint16_t)(mask)) : "memory")
#define TCGEN05_WAIT_LD()  asm volatile("tcgen05.wait::ld.sync.aligned;" ::: "memory")
#define TCGEN05_FENCE_BEFORE() asm volatile("tcgen05.fence::before_thread_sync;" ::: "memory")
#define TCGEN05_FENCE_AFTER()  asm volatile("tcgen05.fence::after_thread_sync;" ::: "memory")
#define FENCE_ASYNC() asm volatile("fence.proxy.async.shared::cta;" ::: "memory")

// cg2 TMA load: both CTAs execute; complete_tx targets the LEADER's barrier
// (clear bit 24 of the cluster-shared barrier address — Sm100MmaPeerBitMask).
#define TMA_LOAD_3D_CG2(smem_addr, tensor_map, cx, cy, cz, mbar) \
    asm volatile("{\n\t" \
        ".reg .b32 leaderBar;\n\t" \
        "and.b32 leaderBar, %5, 0xFEFFFFFF;\n\t" \
        "cp.async.bulk.tensor.3d.cta_group::2.shared::cluster.global" \
        ".tile.mbarrier::complete_tx::bytes " \
        "[%0], [%1, {%2, %3, %4}], [leaderBar];\n\t" \
        "}" \
        :: "r"((uint32_t)(smem_addr)), "l"(tensor_map), \
           "r"((int32_t)(cx)), "r"((int32_t)(cy)), "r"((int32_t)(cz)), \
           "r"((uint32_t)(mbar)) : "memory")

#define TCGEN05_LD_32X32B_X32(r, ta) \
    asm volatile("tcgen05.ld.sync.aligned.32x32b.x32.b32 " \
        "{%0, %1, %2, %3, %4, %5, %6, %7, %8, %9, %10, %11, %12, %13, %14, %15, " \
        " %16, %17, %18, %19, %20, %21, %22, %23, %24, %25, %26, %27, %28, %29, %30, %31}, [%32];" \
        : "=r"((r)[0]),  "=r"((r)[1]),  "=r"((r)[2]),  "=r"((r)[3]), \
          "=r"((r)[4]),  "=r"((r)[5]),  "=r"((r)[6]),  "=r"((r)[7]), \
          "=r"((r)[8]),  "=r"((r)[9]),  "=r"((r)[10]), "=r"((r)[11]), \
          "=r"((r)[12]), "=r"((r)[13]), "=r"((r)[14]), "=r"((r)[15]), \
          "=r"((r)[16]), "=r"((r)[17]), "=r"((r)[18]), "=r"((r)[19]), \
          "=r"((r)[20]), "=r"((r)[21]), "=r"((r)[22]), "=r"((r)[23]), \
          "=r"((r)[24]), "=r"((r)[25]), "=r"((r)[26]), "=r"((r)[27]), \
          "=r"((r)[28]), "=r"((r)[29]), "=r"((r)[30]), "=r"((r)[31]) \
        : "r"(ta))

// K-major SW128 desc: LBO=1, SBO=64 (proven since R4)
static constexpr uint64_t DESC_SW128 =
    (uint64_t(2) << 61) | (uint64_t(1) << 46) | (uint64_t(64) << 32) | (uint64_t(1) << 16);
#define MAKE_DESC(a) (DESC_SW128 | ((uint64_t)((a) >> 4) & 0x3FFF))

// cta_group::2 tf32 SS MMA: M spans both CTAs (A M-halves + B N-halves read
// from both CTAs' SMEM at the same descriptor offsets).
__device__ __forceinline__ void mma_tf32_ss_cg2(uint32_t d, uint64_t ad, uint64_t bd,
                                                uint32_t idesc, uint32_t en) {
    asm volatile("{\n\t.reg .pred p;\n\tsetp.ne.u32 p, %4, 0;\n\t"
        "tcgen05.mma.cta_group::2.kind::tf32 [%0], %1, %2, %3, "
        "{%5, %5, %5, %5, %5, %5, %5, %5}, p;\n\t}"
        :: "r"(d), "l"(ad), "l"(bd), "r"(idesc), "r"(en), "r"(0u) : "memory");
}
#endif // TCGEN_OK

// ---------------- Prep: round X ----------------
__global__ void round_x_kernel(const float4* __restrict__ in) {
    size_t i = (size_t)blockIdx.x * blockDim.x + threadIdx.x;
    float4 v = in[i];
    v.x = rn_tf32(v.x); v.y = rn_tf32(v.y); v.z = rn_tf32(v.z); v.w = rn_tf32(v.w);
    reinterpret_cast<float4*>(g_Xr)[i] = v;
}

// ---------------- Prep: round + transpose weights to [n][k] ----------------
template <int WHICH>
__global__ void transpose_round_kernel(const float* __restrict__ in) {
    constexpr int R = (WHICH == 0) ? H_DIM : I_DIM;  // input rows (k)
    constexpr int C = (WHICH == 0) ? I_DIM : H_DIM;  // input cols (n)
    float* out = (WHICH == 0) ? g_W1t : g_W2t;
    __shared__ float tile[32][33];
    int e = blockIdx.z;
    const float* pin = in + (size_t)e * R * C;
    float* pout = out + (size_t)e * R * C;
    int tx = threadIdx.x, ty = threadIdx.y;
    int c0 = blockIdx.x * 32, r0 = blockIdx.y * 32;
#pragma unroll
    for (int j = 0; j < 4; j++)
        tile[ty + j * 8][tx] = rn_tf32(pin[(size_t)(r0 + ty + j * 8) * C + c0 + tx]);
    __syncthreads();
#pragma unroll
    for (int j = 0; j < 4; j++)
        pout[(size_t)(c0 + ty + j * 8) * R + r0 + tx] = tile[tx][ty + j * 8];
}

// ============================================================================
// Grouped GEMM: C[e,m,n] = sum_k A[e,m,k]*B[e,n,k] + bias[e,n]
// cta_group::2 pair tile 256(M)x256(N), KC=32, STAGES=2, 2 CTAs/SM.
// Each CTA holds its M-half of A (16 KB/stage) and N-half of B (16 KB/stage);
// delivered bytes/CTA/iter: 48->32 KB at same MACs (the R14-identified binder
// is the path-independent LTS delivery cap, so arithmetic intensity is the
// only lever). Both CTAs' TMA completions feed rank0's full barrier (cg2
// leader trick); rank0 issues MMAs; cg2 commit-multicast flips both CTAs'
// empty/done barriers. blockIdx.x = mtPair*2 + rank, cluster (2,1,1).
// WHICH=0: A=g_Xr (K=H), B=g_W1t, N=I, C=g_h (rounded)
// WHICH=1: A=g_h  (K=I), B=g_W2t, N=H, C=out
// ============================================================================
template <int KT, int NTOT, int WHICH>
__global__ __launch_bounds__(256, 2) __cluster_dims__(2, 1, 1)
void gemm_tf32_kernel(const __grid_constant__ CUtensorMap tmA,
                      const __grid_constant__ CUtensorMap tmB,
                      const float* __restrict__ bias, float* __restrict__ outC) {
    constexpr int TMP = 256, TN = 256, KC = 32, STAGES = 2;  // TMP = pair M tile
    constexpr int ABYTES = 128 * KC * 4;   // 16 KB (this CTA's M-half)
    constexpr int BBYTES = 128 * KC * 4;   // 16 KB (this CTA's N-half)
    constexpr int KITERS = KT / KC;

    float* Cb = (WHICH == 0) ? g_h : outC;

    extern __shared__ char smem[];
    uint32_t sbase = smem_to_u32(smem);
    float* bias_s = (float*)(smem + 2048);              // 256 floats
    uint32_t tiles = (sbase + 3072 + 1023) & ~1023u;    // 1024-aligned

    int tid = threadIdx.x, wid = tid >> 5, lane = tid & 31;
    int rank = blockIdx.x & 1;          // == cluster_ctarank for cluster (2,1,1)
    int mt   = blockIdx.x >> 1;         // pair m-tile
    int nt   = blockIdx.y, e = blockIdx.z;

    if (tid < TN) bias_s[tid] = bias[(size_t)e * NTOT + (size_t)nt * TN + tid];

#if TCGEN_OK
    constexpr uint32_t IDESC =
        (1u << 4) | (2u << 7) | (2u << 10) | ((TN / 8) << 17) | ((TMP / 16) << 24);
    uint32_t full0  = sbase;          // STAGES x 8B (used on rank 0 only)
    uint32_t empty0 = sbase + 64;     // STAGES x 8B
    uint32_t doneb  = sbase + 128;
    uint32_t tslot  = sbase + 136;

    if (tid == 0) {
#pragma unroll
        for (int s = 0; s < STAGES; s++) {
            MBARRIER_INIT(full0 + 8 * s, 1);    // rank0: expect_tx arrive + 64KB tx
            MBARRIER_INIT(empty0 + 8 * s, 1);   // one cg2 commit-multicast arrival
        }
        MBARRIER_INIT(doneb, 1);
        FENCE_ASYNC();
    }
    if (wid == 7) {
        TCGEN05_ALLOC_CG2(tslot, 256);   // collective across pair; 256 cols/CTA
        TCGEN05_RELINQ_CG2();            // release permit for co-resident pair
    }
    __syncthreads();
    // peer barriers must exist before cg2 TMA targets rank0's barrier,
    // and peer SMEM tiles before MMA reads them (paced by full-barrier tx)
    CLUSTER_SYNC();

    uint32_t tmem;
    asm volatile("ld.shared.b32 %0, [%1];" : "=r"(tmem) : "r"(tslot));

    if (wid == 6 && elect_one_pred()) {
        // producer (both CTAs): this CTA's A M-half + B N-half, completion -> rank0
#pragma unroll 1
        for (int it = 0; it < KITERS; ++it) {
            int s = it & (STAGES - 1);
            MBARRIER_WAIT_PARITY(empty0 + 8 * s, 1 ^ ((it >> 1) & 1));
            uint32_t fb = full0 + 8 * s;
            if (rank == 0) MBARRIER_EXPECT_TX(fb, 2 * (ABYTES + BBYTES));  // 64 KB/pair
            TMA_LOAD_3D_CG2(tiles + s * ABYTES, &tmA,
                            it * KC, mt * TMP + rank * 128, e, fb);
            TMA_LOAD_3D_CG2(tiles + STAGES * ABYTES + s * BBYTES, &tmB,
                            it * KC, nt * TN + rank * 128, e, fb);
        }
    }
    if (rank == 0 && wid == 7 && elect_one_pred()) {
        // MMA issuer (leader only): M=256 spans both CTAs' SMEM/TMEM
#pragma unroll 1
        for (int it = 0; it < KITERS; ++it) {
            int s = it & (STAGES - 1);
            MBARRIER_WAIT_PARITY(full0 + 8 * s, (it >> 1) & 1);
            uint64_t ad = MAKE_DESC(tiles + s * ABYTES);
            uint64_t bd = MAKE_DESC(tiles + STAGES * ABYTES + s * BBYTES);
#pragma unroll
            for (int k = 0; k < 4; k++)   // 4 x K=8 tf32 dispatches, +32B each
                mma_tf32_ss_cg2(tmem, ad + 2 * k, bd + 2 * k, IDESC,
                                (it > 0 || k > 0) ? 1u : 0u);
            TCGEN05_COMMIT_MULTICAST_CG2(empty0 + 8 * s, 0x3);  // both CTAs' producers
        }
        TCGEN05_COMMIT_MULTICAST_CG2(doneb, 0x3);               // both CTAs' epilogues
    }

    // epilogue: each CTA reads its own TMEM M-half (128 rows x 256 cols)
    if (wid < 4) {
        MBARRIER_WAIT_PARITY(doneb, 0);
        TCGEN05_FENCE_AFTER();
        float* Crow = Cb + ((size_t)(e * T_TOK + mt * TMP + rank * 128 + wid * 32 + lane)) * NTOT
                         + (size_t)nt * TN;
#pragma unroll 1
        for (int c0 = 0; c0 < TN / 32; c0++) {
            uint32_t regs[32];
            TCGEN05_LD_32X32B_X32(regs, tmem + c0 * 32);
            TCGEN05_WAIT_LD();
            float4 v[8];
#pragma unroll
            for (int j = 0; j < 32; j++) {
                float x = __uint_as_float(regs[j]) + bias_s[c0 * 32 + j];
                if (WHICH == 0) x = rn_tf32(x);
                ((float*)v)[j] = x;
            }
#pragma unroll
            for (int q = 0; q < 8; q++)
                reinterpret_cast<float4*>(Crow + c0 * 32)[q] = v[q];
        }
        TCGEN05_FENCE_BEFORE();
    }
    __syncthreads();
    // no CTA may exit while its pair's TMA/commit can still target its SMEM
    CLUSTER_SYNC();
    if (wid == 7) {
        TCGEN05_DEALLOC_CG2(tmem, 256);
    }
#else
    // Fallback (base sm_103 compile pass; never selected at runtime on GB300):
    // correct but slow scalar GEMM so the fat binary stays semantically valid.
    const float* A = (WHICH == 0) ? g_Xr : g_h;
    const float* B = (WHICH == 0) ? g_W1t : g_W2t;
    const float* Ab = A + ((size_t)e * T_TOK + (size_t)(mt * TMP + rank * 128)) * KT;
    const float* Bb = B + ((size_t)e * NTOT + (size_t)nt * TN) * KT;
    __syncthreads();
    for (int idx = tid; idx < 128 * TN; idx += 256) {
        int m = idx / TN, n = idx % TN;
        float s = bias_s[n];
        const float* a = Ab + (size_t)m * KT;
        const float* b = Bb + (size_t)n * KT;
        for (int k = 0; k < KT; k++) s += a[k] * b[k];
        if (WHICH == 0) s = rn_tf32(s);
        Cb[((size_t)(e * T_TOK + mt * TMP + rank * 128 + m)) * NTOT + (size_t)nt * TN + n] = s;
    }
#endif
}

// ---------------- host: tensormap building ----------------
typedef CUresult (*PFN_tmEncode)(CUtensorMap*, CUtensorMapDataType, cuuint32_t, void*,
                                 const cuuint64_t*, const cuuint64_t*, const cuuint32_t*,
                                 const cuuint32_t*, CUtensorMapInterleave, CUtensorMapSwizzle,
                                 CUtensorMapL2promotion, CUtensorMapFloatOOBfill);

static void make_map_f32(PFN_tmEncode enc, CUtensorMap* m, void* base,
                         uint64_t d0, uint64_t d1, uint64_t d2,
                         uint32_t b0, uint32_t b1) {
    cuuint64_t dims[3]    = {d0, d1, d2};
    cuuint64_t strides[2] = {d0 * 4, d0 * d1 * 4};
    cuuint32_t box[3]     = {b0, b1, 1};
    cuuint32_t es[3]      = {1, 1, 1};
    enc(m, CU_TENSOR_MAP_DATA_TYPE_FLOAT32, 3, base, dims, strides, box, es,
        CU_TENSOR_MAP_INTERLEAVE_NONE, CU_TENSOR_MAP_SWIZZLE_128B,
        CU_TENSOR_MAP_L2_PROMOTION_L2_128B, CU_TENSOR_MAP_FLOAT_OOB_FILL_NONE);
}

// ---------------- launch ----------------
extern "C" void kernel_launch(void* const* d_in, const int* in_sizes, int n_in,
                              void* d_out, int out_size) {
    const float* X  = (const float*)d_in[0];
    const float* W1 = (const float*)d_in[1];
    const float* b1 = (const float*)d_in[2];
    const float* W2 = (const float*)d_in[3];
    const float* b2 = (const float*)d_in[4];
    float* out = (float*)d_out;

    // One-time resources (created on the eager correctness call, reused in capture)
    static PFN_tmEncode enc = nullptr;
    static CUtensorMap tmA1, tmB1, tmA2, tmB2;
    constexpr int SMEM = 4096 + 2 * (128 * 32 * 4 + 128 * 32 * 4);  // 69632
    if (!enc) {
        void* fn = nullptr;
        cudaDriverEntryPointQueryResult qres;
        cudaGetDriverEntryPoint("cuTensorMapEncodeTiled", &fn, cudaEnableDefault, &qres);
        enc = (PFN_tmEncode)fn;

        void *pXr = nullptr, *pW1t = nullptr, *pW2t = nullptr, *pH = nullptr;
        cudaGetSymbolAddress(&pXr, g_Xr);
        cudaGetSymbolAddress(&pW1t, g_W1t);
        cudaGetSymbolAddress(&pW2t, g_W2t);
        cudaGetSymbolAddress(&pH, g_h);
        // box = (32 k-floats = 128B, 128 rows) — one CTA's half-tile per load
        make_map_f32(enc, &tmA1, pXr,  H_DIM, T_TOK, E_EXP, 32, 128);  // X   [e][t][h]
        make_map_f32(enc, &tmB1, pW1t, H_DIM, I_DIM, E_EXP, 32, 128);  // W1t [e][i][h]
        make_map_f32(enc, &tmA2, pH,   I_DIM, T_TOK, E_EXP, 32, 128);  // h   [e][t][i]
        make_map_f32(enc, &tmB2, pW2t, I_DIM, H_DIM, E_EXP, 32, 128);  // W2t [e][h][i]

        cudaFuncSetAttribute(gemm_tf32_kernel<H_DIM, I_DIM, 0>,
                             cudaFuncAttributeMaxDynamicSharedMemorySize, SMEM);
        cudaFuncSetAttribute(gemm_tf32_kernel<I_DIM, H_DIM, 1>,
                             cudaFuncAttributeMaxDynamicSharedMemorySize, SMEM);
    }

    // prep (serial, single stream)
    round_x_kernel<<<(E_EXP * T_TOK * H_DIM) / (4 * 256), 256>>>((const float4*)X);
    transpose_round_kernel<0><<<dim3(I_DIM / 32, H_DIM / 32, E_EXP), dim3(32, 8)>>>(W1);
    transpose_round_kernel<1><<<dim3(H_DIM / 32, I_DIM / 32, E_EXP), dim3(32, 8)>>>(W2);

    // GEMM1: h = X @ W1 + b1   (grid 4 x 16 x 16 = 1024 CTAs = 512 cg2 pairs)
    gemm_tf32_kernel<H_DIM, I_DIM, 0>
        <<<dim3(2 * (T_TOK / 256), I_DIM / 256, E_EXP), 256, SMEM>>>(tmA1, tmB1, b1, nullptr);
    // GEMM2: y = h @ W2 + b2   (grid 4 x 4 x 16 = 256 CTAs = 128 pairs)
    gemm_tf32_kernel<I_DIM, H_DIM, 1>
        <<<dim3(2 * (T_TOK / 256), H_DIM / 256, E_EXP), 256, SMEM>>>(tmA2, tmB2, b2, out);
}

// round 17
// speedup vs baseline: 1.1236x; 1.0821x over previous
#include <cuda_runtime.h>
#include <cuda.h>
#include <cstdint>
#include <cstddef>

#define E_EXP 16
#define T_TOK 512
#define H_DIM 1024
#define I_DIM 4096

#if defined(__CUDA_ARCH__) && (defined(__CUDA_ARCH_FEAT_SM103_ALL) || defined(__CUDA_ARCH_FEAT_SM100_ALL) || defined(__CUDA_ARCH_FEAT_SM101_ALL) || defined(__CUDA_ARCH_SPECIFIC__))
#define TCGEN_OK 1
#else
#define TCGEN_OK 0
#endif

// Scratch (__device__ globals: allocation-free rule)
__device__ float g_Xr [(size_t)E_EXP * T_TOK * H_DIM];   // rounded X        [e][t][h]
__device__ float g_W1t[(size_t)E_EXP * I_DIM * H_DIM];   // rounded W1^T     [e][i][h]
__device__ float g_W2t[(size_t)E_EXP * H_DIM * I_DIM];   // rounded W2^T     [e][h][i]
__device__ float g_h  [(size_t)E_EXP * T_TOK * I_DIM];   // intermediate (tf32-rounded)

// ---------------- common helpers ----------------
__device__ __forceinline__ uint32_t smem_to_u32(const void* p) {
    uint32_t a;
    asm("{ .reg .u64 t; cvta.to.shared.u64 t, %1; cvt.u32.u64 %0, t; }" : "=r"(a) : "l"(p));
    return a;
}
// RN-round fp32 -> tf32 bit pattern (low 13 bits zero); exact no-op for HW cvt
__device__ __forceinline__ float rn_tf32(float x) {
    uint32_t b = __float_as_uint(x);
    b = (b + 0xFFFu + ((b >> 13) & 1u)) & 0xFFFFE000u;
    return __uint_as_float(b);
}

#define CLUSTER_SYNC() do { \
    asm volatile("barrier.cluster.arrive.aligned;" ::: "memory"); \
    asm volatile("barrier.cluster.wait.aligned;" ::: "memory"); \
} while (0)

#if TCGEN_OK
// ---------------- tcgen05/TMA helpers (sm_103a pass only) ----------------
__device__ __forceinline__ uint32_t elect_one_pred() {
    uint32_t pred;
    asm volatile("{\n\t.reg .pred p;\n\telect.sync _|p, 0xFFFFFFFF;\n\tselp.b32 %0, 1, 0, p;\n\t}" : "=r"(pred));
    return pred;
}
#define MBARRIER_INIT(addr, count) \
    asm volatile("mbarrier.init.shared.b64 [%0], %1;" :: "r"((uint32_t)(addr)), "r"((uint32_t)(count)) : "memory")
#define MBARRIER_EXPECT_TX(addr, bytes) \
    asm volatile("mbarrier.arrive.expect_tx.shared.b64 _, [%0], %1;" :: "r"((uint32_t)(addr)), "r"((uint32_t)(bytes)) : "memory")
#define MBARRIER_WAIT_PARITY(a, pp) do { \
    uint32_t _m = (uint32_t)(a); uint32_t _p = (uint32_t)(pp); uint32_t _d; \
    asm volatile("{\n\t.reg .pred p;\n\tmbarrier.try_wait.parity.acquire.cta.shared::cta.b64 p, [%1], %2;\n\tselp.b32 %0, 1, 0, p;\n\t}" \
        : "=r"(_d) : "r"(_m), "r"(_p) : "memory"); \
    if (!_d) { \
        asm volatile("{\n\t.reg .pred P1;\n\tWL_%=:\n\tmbarrier.try_wait.parity.acquire.cta.shared::cta.b64 P1, [%0], %1, 0x989680;\n\t@P1 bra.uni WD_%=;\n\tbra.uni WL_%=;\n\tWD_%=:\n\t}" \
            :: "r"(_m), "r"(_p) : "memory"); \
    } \
} while (0)
// cta_group::2 TMEM management (collective across the pair)
#define TCGEN05_ALLOC_CG2(sa, n) \
    asm volatile("tcgen05.alloc.cta_group::2.sync.aligned.shared::cta.b32 [%0], %1;" :: "r"((uint32_t)(sa)), "r"((uint32_t)(n)) : "memory")
#define TCGEN05_DEALLOC_CG2(t, n) \
    asm volatile("tcgen05.dealloc.cta_group::2.sync.aligned.b32 %0, %1;" :: "r"(t), "r"((uint32_t)(n)))
#define TCGEN05_RELINQ_CG2() asm volatile("tcgen05.relinquish_alloc_permit.cta_group::2.sync.aligned;")
#define TCGEN05_COMMIT_MULTICAST_CG2(m, mask) \
    asm volatile("tcgen05.commit.cta_group::2.mbarrier::arrive::one.shared::cluster.multicast::cluster.b64 [%0], %1;" \
                 :: "r"((uint32_t)(m)), "h"((uint16_t)(mask)) : "memory")
#define TCGEN05_WAIT_LD()  asm volatile("tcgen05.wait::ld.sync.aligned;" ::: "memory")
#define TCGEN05_FENCE_BEFORE() asm volatile("tcgen05.fence::before_thread_sync;" ::: "memory")
#define TCGEN05_FENCE_AFTER()  asm volatile("tcgen05.fence::after_thread_sync;" ::: "memory")
#define FENCE_ASYNC() asm volatile("fence.proxy.async.shared::cta;" ::: "memory")

// cg2 TMA load: both CTAs execute; complete_tx targets the LEADER's barrier
// (clear bit 24 of the cluster-shared barrier address — Sm100MmaPeerBitMask).
#define TMA_LOAD_3D_CG2(smem_addr, tensor_map, cx, cy, cz, mbar) \
    asm volatile("{\n\t" \
        ".reg .b32 leaderBar;\n\t" \
        "and.b32 leaderBar, %5, 0xFEFFFFFF;\n\t" \
        "cp.async.bulk.tensor.3d.cta_group::2.shared::cluster.global" \
        ".tile.mbarrier::complete_tx::bytes " \
        "[%0], [%1, {%2, %3, %4}], [leaderBar];\n\t" \
        "}" \
        :: "r"((uint32_t)(smem_addr)), "l"(tensor_map), \
           "r"((int32_t)(cx)), "r"((int32_t)(cy)), "r"((int32_t)(cz)), \
           "r"((uint32_t)(mbar)) : "memory")

#define TCGEN05_LD_32X32B_X32(r, ta) \
    asm volatile("tcgen05.ld.sync.aligned.32x32b.x32.b32 " \
        "{%0, %1, %2, %3, %4, %5, %6, %7, %8, %9, %10, %11, %12, %13, %14, %15, " \
        " %16, %17, %18, %19, %20, %21, %22, %23, %24, %25, %26, %27, %28, %29, %30, %31}, [%32];" \
        : "=r"((r)[0]),  "=r"((r)[1]),  "=r"((r)[2]),  "=r"((r)[3]), \
          "=r"((r)[4]),  "=r"((r)[5]),  "=r"((r)[6]),  "=r"((r)[7]), \
          "=r"((r)[8]),  "=r"((r)[9]),  "=r"((r)[10]), "=r"((r)[11]), \
          "=r"((r)[12]), "=r"((r)[13]), "=r"((r)[14]), "=r"((r)[15]), \
          "=r"((r)[16]), "=r"((r)[17]), "=r"((r)[18]), "=r"((r)[19]), \
          "=r"((r)[20]), "=r"((r)[21]), "=r"((r)[22]), "=r"((r)[23]), \
          "=r"((r)[24]), "=r"((r)[25]), "=r"((r)[26]), "=r"((r)[27]), \
          "=r"((r)[28]), "=r"((r)[29]), "=r"((r)[30]), "=r"((r)[31]) \
        : "r"(ta))

// K-major SW128 desc: LBO=1, SBO=64 (proven since R4)
static constexpr uint64_t DESC_SW128 =
    (uint64_t(2) << 61) | (uint64_t(1) << 46) | (uint64_t(64) << 32) | (uint64_t(1) << 16);
#define MAKE_DESC(a) (DESC_SW128 | ((uint64_t)((a) >> 4) & 0x3FFF))

// cta_group::2 tf32 SS MMA: M spans both CTAs (A M-halves + B N-halves read
// from both CTAs' SMEM at the same descriptor offsets).
__device__ __forceinline__ void mma_tf32_ss_cg2(uint32_t d, uint64_t ad, uint64_t bd,
                                                uint32_t idesc, uint32_t en) {
    asm volatile("{\n\t.reg .pred p;\n\tsetp.ne.u32 p, %4, 0;\n\t"
        "tcgen05.mma.cta_group::2.kind::tf32 [%0], %1, %2, %3, "
        "{%5, %5, %5, %5, %5, %5, %5, %5}, p;\n\t}"
        :: "r"(d), "l"(ad), "l"(bd), "r"(idesc), "r"(en), "r"(0u) : "memory");
}
#endif // TCGEN_OK

// ---------------- Prep: round X ----------------
__global__ void round_x_kernel(const float4* __restrict__ in) {
    size_t i = (size_t)blockIdx.x * blockDim.x + threadIdx.x;
    float4 v = in[i];
    v.x = rn_tf32(v.x); v.y = rn_tf32(v.y); v.z = rn_tf32(v.z); v.w = rn_tf32(v.w);
    reinterpret_cast<float4*>(g_Xr)[i] = v;
}

// ---------------- Prep: round + transpose weights to [n][k] ----------------
template <int WHICH>
__global__ void transpose_round_kernel(const float* __restrict__ in) {
    constexpr int R = (WHICH == 0) ? H_DIM : I_DIM;  // input rows (k)
    constexpr int C = (WHICH == 0) ? I_DIM : H_DIM;  // input cols (n)
    float* out = (WHICH == 0) ? g_W1t : g_W2t;
    __shared__ float tile[32][33];
    int e = blockIdx.z;
    const float* pin = in + (size_t)e * R * C;
    float* pout = out + (size_t)e * R * C;
    int tx = threadIdx.x, ty = threadIdx.y;
    int c0 = blockIdx.x * 32, r0 = blockIdx.y * 32;
#pragma unroll
    for (int j = 0; j < 4; j++)
        tile[ty + j * 8][tx] = rn_tf32(pin[(size_t)(r0 + ty + j * 8) * C + c0 + tx]);
    __syncthreads();
#pragma unroll
    for (int j = 0; j < 4; j++)
        pout[(size_t)(c0 + ty + j * 8) * R + r0 + tx] = tile[tx][ty + j * 8];
}

// ============================================================================
// Grouped GEMM: C[e,m,n] = sum_k A[e,m,k]*B[e,n,k] + bias[e,n]
// cta_group::2 pair tile 256(M)x256(N), KC=32, STAGES=3, 2 CTAs/SM.
// R17 change: STAGES 2->3 (smem 68->100 KB/CTA). With 2 stages the pair had
// only 2x512 cyc of buffered MMA work vs a ~600-cyc TMA refill + cg2
// commit->empty round-trip, so the MMA warp stalled on full[s] every iter.
// 3 stages lets it run a full stage ahead.
// WHICH=0: A=g_Xr (K=H), B=g_W1t, N=I, C=g_h (rounded)
// WHICH=1: A=g_h  (K=I), B=g_W2t, N=H, C=out
// ============================================================================
template <int KT, int NTOT, int WHICH>
__global__ __launch_bounds__(256, 2) __cluster_dims__(2, 1, 1)
void gemm_tf32_kernel(const __grid_constant__ CUtensorMap tmA,
                      const __grid_constant__ CUtensorMap tmB,
                      const float* __restrict__ bias, float* __restrict__ outC) {
    constexpr int TMP = 256, TN = 256, KC = 32, STAGES = 3;  // TMP = pair M tile
    constexpr int ABYTES = 128 * KC * 4;   // 16 KB (this CTA's M-half)
    constexpr int BBYTES = 128 * KC * 4;   // 16 KB (this CTA's N-half)
    constexpr int KITERS = KT / KC;

    float* Cb = (WHICH == 0) ? g_h : outC;

    extern __shared__ char smem[];
    uint32_t sbase = smem_to_u32(smem);
    float* bias_s = (float*)(smem + 2048);              // 256 floats
    uint32_t tiles = (sbase + 3072 + 1023) & ~1023u;    // 1024-aligned

    int tid = threadIdx.x, wid = tid >> 5, lane = tid & 31;
    int rank = blockIdx.x & 1;          // == cluster_ctarank for cluster (2,1,1)
    int mt   = blockIdx.x >> 1;         // pair m-tile
    int nt   = blockIdx.y, e = blockIdx.z;

    if (tid < TN) bias_s[tid] = bias[(size_t)e * NTOT + (size_t)nt * TN + tid];

#if TCGEN_OK
    constexpr uint32_t IDESC =
        (1u << 4) | (2u << 7) | (2u << 10) | ((TN / 8) << 17) | ((TMP / 16) << 24);
    uint32_t full0  = sbase;          // STAGES x 8B (used on rank 0 only)
    uint32_t empty0 = sbase + 64;     // STAGES x 8B
    uint32_t doneb  = sbase + 128;
    uint32_t tslot  = sbase + 136;

    if (tid == 0) {
#pragma unroll
        for (int s = 0; s < STAGES; s++) {
            MBARRIER_INIT(full0 + 8 * s, 1);    // rank0: expect_tx arrive + 64KB tx
            MBARRIER_INIT(empty0 + 8 * s, 1);   // one cg2 commit-multicast arrival
        }
        MBARRIER_INIT(doneb, 1);
        FENCE_ASYNC();
    }
    if (wid == 7) {
        TCGEN05_ALLOC_CG2(tslot, 256);   // collective across pair; 256 cols/CTA
        TCGEN05_RELINQ_CG2();            // release permit for co-resident pair
    }
    __syncthreads();
    // peer barriers must exist before cg2 TMA targets rank0's barrier
    CLUSTER_SYNC();

    uint32_t tmem;
    asm volatile("ld.shared.b32 %0, [%1];" : "=r"(tmem) : "r"(tslot));

    if (wid == 6 && elect_one_pred()) {
        // producer (both CTAs): this CTA's A M-half + B N-half, completion -> rank0
        int s = 0, ph = 0;
#pragma unroll 1
        for (int it = 0; it < KITERS; ++it) {
            MBARRIER_WAIT_PARITY(empty0 + 8 * s, 1 ^ ph);
            uint32_t fb = full0 + 8 * s;
            if (rank == 0) MBARRIER_EXPECT_TX(fb, 2 * (ABYTES + BBYTES));  // 64 KB/pair
            TMA_LOAD_3D_CG2(tiles + s * ABYTES, &tmA,
                            it * KC, mt * TMP + rank * 128, e, fb);
            TMA_LOAD_3D_CG2(tiles + STAGES * ABYTES + s * BBYTES, &tmB,
                            it * KC, nt * TN + rank * 128, e, fb);
            if (++s == STAGES) { s = 0; ph ^= 1; }
        }
    }
    if (rank == 0 && wid == 7 && elect_one_pred()) {
        // MMA issuer (leader only): M=256 spans both CTAs' SMEM/TMEM
        int s = 0, ph = 0;
#pragma unroll 1
        for (int it = 0; it < KITERS; ++it) {
            MBARRIER_WAIT_PARITY(full0 + 8 * s, ph);
            uint64_t ad = MAKE_DESC(tiles + s * ABYTES);
            uint64_t bd = MAKE_DESC(tiles + STAGES * ABYTES + s * BBYTES);
#pragma unroll
            for (int k = 0; k < 4; k++)   // 4 x K=8 tf32 dispatches, +32B each
                mma_tf32_ss_cg2(tmem, ad + 2 * k, bd + 2 * k, IDESC,
                                (it > 0 || k > 0) ? 1u : 0u);
            TCGEN05_COMMIT_MULTICAST_CG2(empty0 + 8 * s, 0x3);  // both CTAs' producers
            if (++s == STAGES) { s = 0; ph ^= 1; }
        }
        TCGEN05_COMMIT_MULTICAST_CG2(doneb, 0x3);               // both CTAs' epilogues
    }

    // epilogue: each CTA reads its own TMEM M-half (128 rows x 256 cols)
    if (wid < 4) {
        MBARRIER_WAIT_PARITY(doneb, 0);
        TCGEN05_FENCE_AFTER();
        float* Crow = Cb + ((size_t)(e * T_TOK + mt * TMP + rank * 128 + wid * 32 + lane)) * NTOT
                         + (size_t)nt * TN;
#pragma unroll 1
        for (int c0 = 0; c0 < TN / 32; c0++) {
            uint32_t regs[32];
            TCGEN05_LD_32X32B_X32(regs, tmem + c0 * 32);
            TCGEN05_WAIT_LD();
            float4 v[8];
#pragma unroll
            for (int j = 0; j < 32; j++) {
                float x = __uint_as_float(regs[j]) + bias_s[c0 * 32 + j];
                if (WHICH == 0) x = rn_tf32(x);
                ((float*)v)[j] = x;
            }
#pragma unroll
            for (int q = 0; q < 8; q++)
                reinterpret_cast<float4*>(Crow + c0 * 32)[q] = v[q];
        }
        TCGEN05_FENCE_BEFORE();
    }
    __syncthreads();
    // no CTA may exit while its pair's TMA/commit can still target its SMEM
    CLUSTER_SYNC();
    if (wid == 7) {
        TCGEN05_DEALLOC_CG2(tmem, 256);
    }
#else
    // Fallback (base sm_103 compile pass; never selected at runtime on GB300):
    // correct but slow scalar GEMM so the fat binary stays semantically valid.
    const float* A = (WHICH == 0) ? g_Xr : g_h;
    const float* B = (WHICH == 0) ? g_W1t : g_W2t;
    const float* Ab = A + ((size_t)e * T_TOK + (size_t)(mt * TMP + rank * 128)) * KT;
    const float* Bb = B + ((size_t)e * NTOT + (size_t)nt * TN) * KT;
    __syncthreads();
    for (int idx = tid; idx < 128 * TN; idx += 256) {
        int m = idx / TN, n = idx % TN;
        float s = bias_s[n];
        const float* a = Ab + (size_t)m * KT;
        const float* b = Bb + (size_t)n * KT;
        for (int k = 0; k < KT; k++) s += a[k] * b[k];
        if (WHICH == 0) s = rn_tf32(s);
        Cb[((size_t)(e * T_TOK + mt * TMP + rank * 128 + m)) * NTOT + (size_t)nt * TN + n] = s;
    }
#endif
}

// ---------------- host: tensormap building ----------------
typedef CUresult (*PFN_tmEncode)(CUtensorMap*, CUtensorMapDataType, cuuint32_t, void*,
                                 const cuuint64_t*, const cuuint64_t*, const cuuint32_t*,
                                 const cuuint32_t*, CUtensorMapInterleave, CUtensorMapSwizzle,
                                 CUtensorMapL2promotion, CUtensorMapFloatOOBfill);

static void make_map_f32(PFN_tmEncode enc, CUtensorMap* m, void* base,
                         uint64_t d0, uint64_t d1, uint64_t d2,
                         uint32_t b0, uint32_t b1) {
    cuuint64_t dims[3]    = {d0, d1, d2};
    cuuint64_t strides[2] = {d0 * 4, d0 * d1 * 4};
    cuuint32_t box[3]     = {b0, b1, 1};
    cuuint32_t es[3]      = {1, 1, 1};
    enc(m, CU_TENSOR_MAP_DATA_TYPE_FLOAT32, 3, base, dims, strides, box, es,
        CU_TENSOR_MAP_INTERLEAVE_NONE, CU_TENSOR_MAP_SWIZZLE_128B,
        CU_TENSOR_MAP_L2_PROMOTION_L2_128B, CU_TENSOR_MAP_FLOAT_OOB_FILL_NONE);
}

// ---------------- launch ----------------
extern "C" void kernel_launch(void* const* d_in, const int* in_sizes, int n_in,
                              void* d_out, int out_size) {
    const float* X  = (const float*)d_in[0];
    const float* W1 = (const float*)d_in[1];
    const float* b1 = (const float*)d_in[2];
    const float* W2 = (const float*)d_in[3];
    const float* b2 = (const float*)d_in[4];
    float* out = (float*)d_out;

    // One-time resources (created on the eager correctness call, reused in capture)
    static PFN_tmEncode enc = nullptr;
    static CUtensorMap tmA1, tmB1, tmA2, tmB2;
    constexpr int SMEM = 4096 + 3 * (128 * 32 * 4 + 128 * 32 * 4);  // 102400
    if (!enc) {
        void* fn = nullptr;
        cudaDriverEntryPointQueryResult qres;
        cudaGetDriverEntryPoint("cuTensorMapEncodeTiled", &fn, cudaEnableDefault, &qres);
        enc = (PFN_tmEncode)fn;

        void *pXr = nullptr, *pW1t = nullptr, *pW2t = nullptr, *pH = nullptr;
        cudaGetSymbolAddress(&pXr, g_Xr);
        cudaGetSymbolAddress(&pW1t, g_W1t);
        cudaGetSymbolAddress(&pW2t, g_W2t);
        cudaGetSymbolAddress(&pH, g_h);
        // box = (32 k-floats = 128B, 128 rows) — one CTA's half-tile per load
        make_map_f32(enc, &tmA1, pXr,  H_DIM, T_TOK, E_EXP, 32, 128);  // X   [e][t][h]
        make_map_f32(enc, &tmB1, pW1t, H_DIM, I_DIM, E_EXP, 32, 128);  // W1t [e][i][h]
        make_map_f32(enc, &tmA2, pH,   I_DIM, T_TOK, E_EXP, 32, 128);  // h   [e][t][i]
        make_map_f32(enc, &tmB2, pW2t, I_DIM, H_DIM, E_EXP, 32, 128);  // W2t [e][h][i]

        cudaFuncSetAttribute(gemm_tf32_kernel<H_DIM, I_DIM, 0>,
                             cudaFuncAttributeMaxDynamicSharedMemorySize, SMEM);
        cudaFuncSetAttribute(gemm_tf32_kernel<I_DIM, H_DIM, 1>,
                             cudaFuncAttributeMaxDynamicSharedMemorySize, SMEM);
    }

    // prep (serial, single stream)
    round_x_kernel<<<(E_EXP * T_TOK * H_DIM) / (4 * 256), 256>>>((const float4*)X);
    transpose_round_kernel<0><<<dim3(I_DIM / 32, H_DIM / 32, E_EXP), dim3(32, 8)>>>(W1);
    transpose_round_kernel<1><<<dim3(H_DIM / 32, I_DIM / 32, E_EXP), dim3(32, 8)>>>(W2);

    // GEMM1: h = X @ W1 + b1   (grid 4 x 16 x 16 = 1024 CTAs = 512 cg2 pairs)
    gemm_tf32_kernel<H_DIM, I_DIM, 0>
        <<<dim3(2 * (T_TOK / 256), I_DIM / 256, E_EXP), 256, SMEM>>>(tmA1, tmB1, b1, nullptr);
    // GEMM2: y = h @ W2 + b2   (grid 4 x 4 x 16 = 256 CTAs = 128 pairs)
    gemm_tf32_kernel<I_DIM, H_DIM, 1>
        <<<dim3(2 * (T_TOK / 256), H_DIM / 256, E_EXP), 256, SMEM>>>(tmA2, tmB2, b2, out);
}